// round 1
// baseline (speedup 1.0000x reference)
#include <cuda_runtime.h>

// Problem constants
#define N 256
#define H 1024
#define M 256
#define ZLEN (M + N)   // 512

// Scratch (allocation-free rule: __device__ globals)
__device__ float g_r1[N * H];   // 1 MB
__device__ float g_r2[N * M];   // 256 KB
__device__ float g_h [N * H];   // 1 MB

__device__ __forceinline__ float warp_reduce(float v) {
    #pragma unroll
    for (int o = 16; o > 0; o >>= 1)
        v += __shfl_xor_sync(0xffffffffu, v, o);
    return v;
}

__device__ __forceinline__ float dot4(float4 a, float4 b) {
    return a.x * b.x + a.y * b.y + a.z * b.z + a.w * b.w;
}

// Kernel 1: r1[n,h] = relu( sum_j W1[n,h,j] * x[j] * (j != n) )
// grid (H/8, N), block 256: 8 warps, one output row each.
__global__ __launch_bounds__(256) void k1_w1(
    const float* __restrict__ W1, const float* __restrict__ x,
    float* __restrict__ r1)
{
    const int n   = blockIdx.y;
    const int tid = threadIdx.x;
    __shared__ float4 xs[N / 4];   // masked x: 64 float4

    if (tid < N / 4) {
        float4 v = reinterpret_cast<const float4*>(x)[tid];
        const int base = tid * 4;
        if (n == base + 0) v.x = 0.f;
        if (n == base + 1) v.y = 0.f;
        if (n == base + 2) v.z = 0.f;
        if (n == base + 3) v.w = 0.f;
        xs[tid] = v;
    }
    __syncthreads();

    const int wid  = tid >> 5;
    const int lane = tid & 31;
    const int h    = blockIdx.x * 8 + wid;

    const float4* Wrow = reinterpret_cast<const float4*>(
        W1 + ((size_t)n * H + h) * N);

    float acc = 0.f;
    #pragma unroll
    for (int k = 0; k < N / 4 / 32; k++)     // 2 iters
        acc += dot4(Wrow[lane + k * 32], xs[lane + k * 32]);

    acc = warp_reduce(acc);
    if (lane == 0) r1[n * H + h] = fmaxf(acc, 0.f);
}

// Kernel 2: r2[n,m] = relu( W2[n,m,:] . r1[n,:] )
// grid (M/8, N), block 256.
__global__ __launch_bounds__(256) void k2_w2(
    const float* __restrict__ W2, const float* __restrict__ r1,
    float* __restrict__ r2)
{
    const int n   = blockIdx.y;
    const int tid = threadIdx.x;
    __shared__ float4 vs[H / 4];   // 256 float4 = 4 KB

    vs[tid] = reinterpret_cast<const float4*>(r1 + (size_t)n * H)[tid];
    __syncthreads();

    const int wid  = tid >> 5;
    const int lane = tid & 31;
    const int m    = blockIdx.x * 8 + wid;

    const float4* Wrow = reinterpret_cast<const float4*>(
        W2 + ((size_t)n * M + m) * H);

    float acc = 0.f;
    #pragma unroll
    for (int k = 0; k < H / 4 / 32; k++)     // 8 iters
        acc += dot4(Wrow[lane + k * 32], vs[lane + k * 32]);

    acc = warp_reduce(acc);
    if (lane == 0) r2[n * M + m] = fmaxf(acc, 0.f);
}

// Kernel 3: h[n,hh] = relu( W3[n,hh,:] . z + b3[n,hh] ),
// z = concat(r2[n,:], onehot(n)*x[n])
// grid (H/8, N), block 256.
__global__ __launch_bounds__(256) void k3_w3(
    const float* __restrict__ W3, const float* __restrict__ b3,
    const float* __restrict__ r2, const float* __restrict__ x,
    float* __restrict__ hbuf)
{
    const int n   = blockIdx.y;
    const int tid = threadIdx.x;
    __shared__ float zs[ZLEN];     // 512 floats = 2 KB

    zs[tid]       = r2[(size_t)n * M + tid];          // first 256
    zs[M + tid]   = (tid == n) ? x[n] : 0.f;          // second 256
    __syncthreads();

    const int wid  = tid >> 5;
    const int lane = tid & 31;
    const int hh   = blockIdx.x * 8 + wid;

    const float4* Wrow = reinterpret_cast<const float4*>(
        W3 + ((size_t)n * H + hh) * ZLEN);
    const float4* vs = reinterpret_cast<const float4*>(zs);

    float acc = 0.f;
    #pragma unroll
    for (int k = 0; k < ZLEN / 4 / 32; k++)  // 4 iters
        acc += dot4(Wrow[lane + k * 32], vs[lane + k * 32]);

    acc = warp_reduce(acc);
    if (lane == 0) hbuf[n * H + hh] = fmaxf(acc + b3[n * H + hh], 0.f);
}

// Kernel 4: out[n] = relu( W4[n,0,:] . h[n,:] + b4[n] )
// grid (N/8), block 256.
__global__ __launch_bounds__(256) void k4_w4(
    const float* __restrict__ W4, const float* __restrict__ b4,
    const float* __restrict__ hbuf, float* __restrict__ out)
{
    const int tid  = threadIdx.x;
    const int wid  = tid >> 5;
    const int lane = tid & 31;
    const int n    = blockIdx.x * 8 + wid;

    const float4* Wrow = reinterpret_cast<const float4*>(W4 + (size_t)n * H);
    const float4* vs   = reinterpret_cast<const float4*>(hbuf + (size_t)n * H);

    float acc = 0.f;
    #pragma unroll
    for (int k = 0; k < H / 4 / 32; k++)     // 8 iters
        acc += dot4(Wrow[lane + k * 32], vs[lane + k * 32]);

    acc = warp_reduce(acc);
    if (lane == 0) out[n] = fmaxf(acc + b4[n], 0.f);
}

extern "C" void kernel_launch(void* const* d_in, const int* in_sizes, int n_in,
                              void* d_out, int out_size)
{
    // Input order (metadata): x, W1, W2, W3, b3, W4, b4, t
    const float* x  = (const float*)d_in[0];
    const float* W1 = (const float*)d_in[1];
    const float* W2 = (const float*)d_in[2];
    const float* W3 = (const float*)d_in[3];
    const float* b3 = (const float*)d_in[4];
    const float* W4 = (const float*)d_in[5];
    const float* b4 = (const float*)d_in[6];
    float* out = (float*)d_out;

    float *r1, *r2, *hb;
    cudaGetSymbolAddress((void**)&r1, g_r1);
    cudaGetSymbolAddress((void**)&r2, g_r2);
    cudaGetSymbolAddress((void**)&hb, g_h);

    k1_w1<<<dim3(H / 8, N), 256>>>(W1, x, r1);
    k2_w2<<<dim3(M / 8, N), 256>>>(W2, r1, r2);
    k3_w3<<<dim3(H / 8, N), 256>>>(W3, b3, r2, x, hb);
    k4_w4<<<N / 8, 256>>>(W4, b4, hb, out);
}

// round 2
// speedup vs baseline: 1.2404x; 1.2404x over previous
#include <cuda_runtime.h>

// Problem constants
#define N 256
#define H 1024
#define M 256
#define ZLEN (M + N)   // 512
#define K3_BLOCKS_PER_N (H / 8)   // 128

// Scratch (allocation-free rule: __device__ globals)
__device__ float g_r1[N * H];                 // 1 MB
__device__ float g_r2[N * M];                 // 256 KB
__device__ float g_part[N * K3_BLOCKS_PER_N]; // 128 KB : per-block W4 partials

__device__ __forceinline__ float warp_reduce(float v) {
    #pragma unroll
    for (int o = 16; o > 0; o >>= 1)
        v += __shfl_xor_sync(0xffffffffu, v, o);
    return v;
}

__device__ __forceinline__ float dot4(float4 a, float4 b) {
    return a.x * b.x + a.y * b.y + a.z * b.z + a.w * b.w;
}

// Kernel 1: r1[n,h] = relu( sum_j W1[n,h,j] * x[j] * (j != n) )
// grid (H/8, N), block 256: 8 warps, one output row each.
__global__ __launch_bounds__(256) void k1_w1(
    const float* __restrict__ W1, const float* __restrict__ x,
    float* __restrict__ r1)
{
    const int n   = blockIdx.y;
    const int tid = threadIdx.x;
    __shared__ float4 xs[N / 4];   // masked x: 64 float4

    if (tid < N / 4) {
        float4 v = reinterpret_cast<const float4*>(x)[tid];
        const int base = tid * 4;
        if (n == base + 0) v.x = 0.f;
        if (n == base + 1) v.y = 0.f;
        if (n == base + 2) v.z = 0.f;
        if (n == base + 3) v.w = 0.f;
        xs[tid] = v;
    }
    __syncthreads();

    const int wid  = tid >> 5;
    const int lane = tid & 31;
    const int h    = blockIdx.x * 8 + wid;

    const float4* Wrow = reinterpret_cast<const float4*>(
        W1 + ((size_t)n * H + h) * N);

    float acc = 0.f;
    #pragma unroll
    for (int k = 0; k < N / 4 / 32; k++)     // 2 iters
        acc += dot4(__ldcs(Wrow + lane + k * 32), xs[lane + k * 32]);

    acc = warp_reduce(acc);
    if (lane == 0) r1[n * H + h] = fmaxf(acc, 0.f);
}

// Kernel 2: r2[n,m] = relu( W2[n,m,:] . r1[n,:] )
// grid (M/8, N), block 256.
__global__ __launch_bounds__(256) void k2_w2(
    const float* __restrict__ W2, const float* __restrict__ r1,
    float* __restrict__ r2)
{
    const int n   = blockIdx.y;
    const int tid = threadIdx.x;
    __shared__ float4 vs[H / 4];   // 256 float4 = 4 KB

    vs[tid] = reinterpret_cast<const float4*>(r1 + (size_t)n * H)[tid];
    __syncthreads();

    const int wid  = tid >> 5;
    const int lane = tid & 31;
    const int m    = blockIdx.x * 8 + wid;

    const float4* Wrow = reinterpret_cast<const float4*>(
        W2 + ((size_t)n * M + m) * H);

    float acc = 0.f;
    #pragma unroll
    for (int k = 0; k < H / 4 / 32; k++)     // 8 iters
        acc += dot4(__ldcs(Wrow + lane + k * 32), vs[lane + k * 32]);

    acc = warp_reduce(acc);
    if (lane == 0) r2[n * M + m] = fmaxf(acc, 0.f);
}

// Kernel 3 (fused with W4 dot):
//   h[n,hh] = relu( W3[n,hh,0:M] . r2[n,:] + W3[n,hh,M+n]*x[n] + b3[n,hh] )
//   part[n, blk] = sum over block's 8 hh of W4[n,hh] * h[n,hh]
// Key: the second half of z is one-hot, so only column M+n of W3[:, :, M:]
// is read — skips ~255 MB of W3 traffic.
// grid (H/8, N), block 256.
__global__ __launch_bounds__(256) void k3_w3w4(
    const float* __restrict__ W3, const float* __restrict__ b3,
    const float* __restrict__ W4, const float* __restrict__ r2,
    const float* __restrict__ x, float* __restrict__ part)
{
    const int n   = blockIdx.y;
    const int tid = threadIdx.x;
    __shared__ float4 zs[M / 4];   // 64 float4 = r2[n,:]
    __shared__ float  hv[8];

    if (tid < M / 4)
        zs[tid] = reinterpret_cast<const float4*>(r2 + (size_t)n * M)[tid];
    __syncthreads();

    const int wid  = tid >> 5;
    const int lane = tid & 31;
    const int hh   = blockIdx.x * 8 + wid;

    const float* Wrow = W3 + ((size_t)n * H + hh) * ZLEN;
    const float4* Wrow4 = reinterpret_cast<const float4*>(Wrow);

    float acc = 0.f;
    #pragma unroll
    for (int k = 0; k < M / 4 / 32; k++)     // 2 iters over first M cols
        acc += dot4(__ldcs(Wrow4 + lane + k * 32), zs[lane + k * 32]);

    acc = warp_reduce(acc);
    if (lane == 0) {
        // one-hot contribution + bias, relu, then fold in W4
        float hval = fmaxf(acc + Wrow[M + n] * x[n] + b3[(size_t)n * H + hh], 0.f);
        hv[wid] = hval * W4[(size_t)n * H + hh];
    }
    __syncthreads();

    if (tid == 0) {
        float s = 0.f;
        #pragma unroll
        for (int i = 0; i < 8; i++) s += hv[i];
        part[(size_t)n * K3_BLOCKS_PER_N + blockIdx.x] = s;
    }
}

// Epilogue: out[n] = relu( sum_blk part[n,blk] + b4[n] )
// grid (N/8), block 256: one warp per n, deterministic reduce.
__global__ __launch_bounds__(256) void k4_fin(
    const float* __restrict__ part, const float* __restrict__ b4,
    float* __restrict__ out)
{
    const int tid  = threadIdx.x;
    const int wid  = tid >> 5;
    const int lane = tid & 31;
    const int n    = blockIdx.x * 8 + wid;

    const float* p = part + (size_t)n * K3_BLOCKS_PER_N;
    float s = 0.f;
    #pragma unroll
    for (int k = 0; k < K3_BLOCKS_PER_N / 32; k++)   // 4 iters
        s += p[lane + k * 32];

    s = warp_reduce(s);
    if (lane == 0) out[n] = fmaxf(s + b4[n], 0.f);
}

extern "C" void kernel_launch(void* const* d_in, const int* in_sizes, int n_in,
                              void* d_out, int out_size)
{
    // Input order (metadata): x, W1, W2, W3, b3, W4, b4, t
    const float* x  = (const float*)d_in[0];
    const float* W1 = (const float*)d_in[1];
    const float* W2 = (const float*)d_in[2];
    const float* W3 = (const float*)d_in[3];
    const float* b3 = (const float*)d_in[4];
    const float* W4 = (const float*)d_in[5];
    const float* b4 = (const float*)d_in[6];
    float* out = (float*)d_out;

    float *r1, *r2, *part;
    cudaGetSymbolAddress((void**)&r1, g_r1);
    cudaGetSymbolAddress((void**)&r2, g_r2);
    cudaGetSymbolAddress((void**)&part, g_part);

    k1_w1<<<dim3(H / 8, N), 256>>>(W1, x, r1);
    k2_w2<<<dim3(M / 8, N), 256>>>(W2, r1, r2);
    k3_w3w4<<<dim3(H / 8, N), 256>>>(W3, b3, W4, r2, x, part);
    k4_fin<<<N / 8, 256>>>(part, b4, out);
}

// round 3
// speedup vs baseline: 1.3854x; 1.1169x over previous
#include <cuda_runtime.h>

// Problem constants
#define N 256
#define H 1024
#define M 256
#define ZLEN (M + N)   // 512
#define NT 512         // threads per block
#define NW (NT / 32)   // 16 warps

__device__ __forceinline__ float warp_reduce(float v) {
    #pragma unroll
    for (int o = 16; o > 0; o >>= 1)
        v += __shfl_xor_sync(0xffffffffu, v, o);
    return v;
}

__device__ __forceinline__ float dot4(float4 a, float4 b) {
    return a.x * b.x + a.y * b.y + a.z * b.z + a.w * b.w;
}

// One block per node n. Whole pipeline in one kernel; intermediates in smem.
//   phase1: r1[h] = relu(W1[n,h,:] . xmask)            (H outputs)
//   phase2: r2[m] = relu(W2[n,m,:] . r1)               (M outputs)
//   phase3: h[hh] = relu(W3[n,hh,0:M].r2 + W3[n,hh,M+n]*x[n] + b3[n,hh])
//           acc  += W4[n,hh] * h[hh]                   (folded, no h buffer)
//   out[n] = relu(acc + b4[n])
__global__ __launch_bounds__(NT, 2) void fused_all(
    const float* __restrict__ x,
    const float* __restrict__ W1, const float* __restrict__ W2,
    const float* __restrict__ W3, const float* __restrict__ b3,
    const float* __restrict__ W4, const float* __restrict__ b4,
    float* __restrict__ out)
{
    const int n    = blockIdx.x;
    const int tid  = threadIdx.x;
    const int wid  = tid >> 5;
    const int lane = tid & 31;

    __shared__ float4 xs4[N / 4];   // masked x   (1 KB)
    __shared__ float4 r1s[H / 4];   // r1         (4 KB)
    __shared__ float4 r2s[M / 4];   // r2         (1 KB)
    __shared__ float  wsum[NW];

    // Load masked x: row n zeroed
    if (tid < N / 4) {
        float4 v = reinterpret_cast<const float4*>(x)[tid];
        const int base = tid * 4;
        if (n == base + 0) v.x = 0.f;
        if (n == base + 1) v.y = 0.f;
        if (n == base + 2) v.z = 0.f;
        if (n == base + 3) v.w = 0.f;
        xs4[tid] = v;
    }
    __syncthreads();

    // ---- Phase 1: r1 = relu(W1[n] @ xmask), warp-per-row, strided rows ----
    {
        const float4* W1b = reinterpret_cast<const float4*>(
            W1 + (size_t)n * H * N);
        float* r1f = reinterpret_cast<float*>(r1s);
        #pragma unroll 4
        for (int i = 0; i < H / NW; i++) {      // 64 rows per warp
            const int h = wid + i * NW;
            const float4* row = W1b + (size_t)h * (N / 4);
            float acc = dot4(__ldcs(row + lane),      xs4[lane])
                      + dot4(__ldcs(row + lane + 32), xs4[lane + 32]);
            acc = warp_reduce(acc);
            if (lane == 0) r1f[h] = fmaxf(acc, 0.f);
        }
    }
    __syncthreads();

    // ---- Phase 2: r2 = relu(W2[n] @ r1) ----
    {
        const float4* W2b = reinterpret_cast<const float4*>(
            W2 + (size_t)n * M * H);
        float* r2f = reinterpret_cast<float*>(r2s);
        #pragma unroll
        for (int i = 0; i < M / NW; i++) {      // 16 rows per warp
            const int m = wid + i * NW;
            const float4* row = W2b + (size_t)m * (H / 4);
            float acc = 0.f;
            #pragma unroll
            for (int k = 0; k < H / 4 / 32; k++)    // 8 float4 per lane
                acc += dot4(__ldcs(row + lane + k * 32), r1s[lane + k * 32]);
            acc = warp_reduce(acc);
            if (lane == 0) r2f[m] = fmaxf(acc, 0.f);
        }
    }
    __syncthreads();

    // ---- Phase 3: h = relu(W3[:,0:M].r2 + onehot + b3); fold W4 ----
    {
        const float* W3b = W3 + (size_t)n * H * ZLEN;
        const float* b3b = b3 + (size_t)n * H;
        const float* W4b = W4 + (size_t)n * H;
        const float  xn  = reinterpret_cast<const float*>(xs4)[0] * 0.f + x[n];

        float wacc = 0.f;   // meaningful on lane 0 only
        #pragma unroll 4
        for (int i = 0; i < H / NW; i++) {      // 64 rows per warp
            const int hh = wid + i * NW;
            const float* rowf = W3b + (size_t)hh * ZLEN;
            const float4* row = reinterpret_cast<const float4*>(rowf);
            float acc = dot4(__ldcs(row + lane),      r2s[lane])
                      + dot4(__ldcs(row + lane + 32), r2s[lane + 32]);
            acc = warp_reduce(acc);
            if (lane == 0) {
                float hv = fmaxf(acc + rowf[M + n] * xn + b3b[hh], 0.f);
                wacc += hv * W4b[hh];
            }
        }
        if (lane == 0) wsum[wid] = wacc;
    }
    __syncthreads();

    if (tid == 0) {
        float s = 0.f;
        #pragma unroll
        for (int i = 0; i < NW; i++) s += wsum[i];
        out[n] = fmaxf(s + b4[n], 0.f);
    }
}

extern "C" void kernel_launch(void* const* d_in, const int* in_sizes, int n_in,
                              void* d_out, int out_size)
{
    // Input order (metadata): x, W1, W2, W3, b3, W4, b4, t
    const float* x  = (const float*)d_in[0];
    const float* W1 = (const float*)d_in[1];
    const float* W2 = (const float*)d_in[2];
    const float* W3 = (const float*)d_in[3];
    const float* b3 = (const float*)d_in[4];
    const float* W4 = (const float*)d_in[5];
    const float* b4 = (const float*)d_in[6];
    float* out = (float*)d_out;

    fused_all<<<N, NT>>>(x, W1, W2, W3, b3, W4, b4, out);
}